// round 9
// baseline (speedup 1.0000x reference)
#include <cuda_runtime.h>
#include <math.h>

#define BB   4
#define NPTS 4096
#define GG   4096
#define KNN  8
#define HH   64
#define EPSBN 1e-5f

// ---------------- scratch (static device globals; no allocations) ----------------
__device__ int   g_idx [BB*GG*KNN];
__device__ float g_vol [BB*HH*GG];     // buffer id 0
__device__ float g_tmp [BB*HH*GG];     // buffer id 1
__device__ float g_h1  [BB*HH*GG];     // buffer id 2
__device__ float g_vol8[BB*HH*512];    // buffer id 3
__device__ float g_st1 [6*64];         // per-channel sum   (stat slots)
__device__ float g_st2 [6*64];         // per-channel sumsq
__device__ float g_pooled[BB*64];

__device__ __forceinline__ float* pick(int id) {
    switch (id) {
        case 0: return g_vol;
        case 1: return g_tmp;
        case 2: return g_h1;
        default: return g_vol8;
    }
}

__device__ __forceinline__ float gelu_tanh(float x) {
    float x3 = x * x * x;
    float t  = tanhf(0.7978845608028654f * (x + 0.044715f * x3));
    return 0.5f * x * (1.0f + t);
}

// -------- packed f32x2 helpers (MLP only: operands naturally pair-resident) --------
typedef unsigned long long ull;
__device__ __forceinline__ ull pk(float lo, float hi) {
    ull r; asm("mov.b64 %0, {%1,%2};" : "=l"(r) : "f"(lo), "f"(hi)); return r;
}
__device__ __forceinline__ ull pk2(float2 f) { return pk(f.x, f.y); }
__device__ __forceinline__ void upk(ull v, float& lo, float& hi) {
    asm("mov.b64 {%0,%1}, %2;" : "=f"(lo), "=f"(hi) : "l"(v));
}
__device__ __forceinline__ ull fma2(ull a, ull b, ull c) {
    ull d; asm("fma.rn.f32x2 %0, %1, %2, %3;" : "=l"(d) : "l"(a), "l"(b), "l"(c)); return d;
}

// ---------------- KNN: 2 threads per voxel, stable merge ----------------
__global__ void knn_kernel(const float* __restrict__ pos) {
    __shared__ float4 tile[2][64];
    __shared__ float  sbd[128][KNN];
    __shared__ int    sbi[128][KNN];

    if (blockIdx.x == 0) {
        for (int i = threadIdx.x; i < 6 * 64; i += 128) { g_st1[i] = 0.0f; g_st2[i] = 0.0f; }
    }

    int b   = blockIdx.x >> 6;
    int vl  = threadIdx.x & 63;
    int half= threadIdx.x >> 6;
    int g   = ((blockIdx.x & 63) << 6) + vl;

    int gi = g >> 8, gj = (g >> 4) & 15, gk = g & 15;
    const float step = 2.0f / 15.0f;
    float gx = -1.0f + step * gi;
    float gy = -1.0f + step * gj;
    float gz = -1.0f + step * gk;
    float ax = -2.0f * gx, ay = -2.0f * gy, az = -2.0f * gz;

    float bd[KNN]; int bi[KNN];
#pragma unroll
    for (int j = 0; j < KNN; j++) { bd[j] = 3.4e38f; bi[j] = 0; }

    const float* pb = pos + ((size_t)b * NPTS + half * 2048) * 3;

    for (int t0 = 0; t0 < 2048; t0 += 64) {
        __syncthreads();
        {
            int n = t0 + vl;
            float px = pb[n * 3 + 0], py = pb[n * 3 + 1], pz = pb[n * 3 + 2];
            tile[half][vl] = make_float4(px, py, pz, px * px + py * py + pz * pz);
        }
        __syncthreads();
#pragma unroll 2
        for (int t = 0; t < 64; t += 2) {
            float4 p = tile[half][t];
            float4 q = tile[half][t + 1];
            float e0 = fmaf(ax, p.x, fmaf(ay, p.y, fmaf(az, p.z, p.w)));
            float e1 = fmaf(ax, q.x, fmaf(ay, q.y, fmaf(az, q.z, q.w)));
            if (e0 < bd[KNN - 1]) {
                int n = half * 2048 + t0 + t;
#pragma unroll
                for (int j = KNN - 1; j >= 1; --j) {
                    if (e0 < bd[j - 1])  { bd[j] = bd[j - 1]; bi[j] = bi[j - 1]; }
                    else if (e0 < bd[j]) { bd[j] = e0;        bi[j] = n; }
                }
                if (e0 < bd[0]) { bd[0] = e0; bi[0] = n; }
            }
            if (e1 < bd[KNN - 1]) {
                int n = half * 2048 + t0 + t + 1;
#pragma unroll
                for (int j = KNN - 1; j >= 1; --j) {
                    if (e1 < bd[j - 1])  { bd[j] = bd[j - 1]; bi[j] = bi[j - 1]; }
                    else if (e1 < bd[j]) { bd[j] = e1;        bi[j] = n; }
                }
                if (e1 < bd[0]) { bd[0] = e1; bi[0] = n; }
            }
        }
    }

#pragma unroll
    for (int j = 0; j < KNN; j++) { sbd[threadIdx.x][j] = bd[j]; sbi[threadIdx.x][j] = bi[j]; }
    __syncthreads();

    if (threadIdx.x < 64) {
        int ia = 0, ibp = 0;
        int base = (b * GG + g) * KNN;
#pragma unroll
        for (int j = 0; j < KNN; j++) {
            float eA = sbd[threadIdx.x][ia], eB = sbd[threadIdx.x + 64][ibp];
            if (eA <= eB) { g_idx[base + j] = sbi[threadIdx.x][ia]; ia++; }
            else          { g_idx[base + j] = sbi[threadIdx.x + 64][ibp]; ibp++; }
        }
    }
}

// ---------------- Bipartite conv MLP: 8 voxels per block (weights amortized) --------
// 2048 blocks x 64 threads. Phase 1: pe_w2 column in regs, 8-voxel neighbor loop.
// Phase 2: regs reloaded with up_w column, 8 update dots + gelu + store.
__global__ void mlp_kernel(const float* __restrict__ pos, const float* __restrict__ xf,
                           const float* __restrict__ pe_w1, const float* __restrict__ pe_b1,
                           const float* __restrict__ pe_w2, const float* __restrict__ pe_b2,
                           const float* __restrict__ f_w,   const float* __restrict__ f_b,
                           const float* __restrict__ up_w,  const float* __restrict__ up_b) {
    __shared__ float s_w1[192], s_fw[192];
    __shared__ float s_b1[64], s_b2[64], s_fb[64], s_ub[64];
    __shared__ __align__(8) float s_t[64];

    int h = threadIdx.x;
    s_w1[h] = pe_w1[h];       s_w1[h + 64] = pe_w1[h + 64];   s_w1[h + 128] = pe_w1[h + 128];
    s_fw[h] = f_w[h];         s_fw[h + 64] = f_w[h + 64];     s_fw[h + 128] = f_w[h + 128];
    s_b1[h] = pe_b1[h]; s_b2[h] = pe_b2[h]; s_fb[h] = f_b[h]; s_ub[h] = up_b[h];

    ull wcol2[32];
#pragma unroll
    for (int j = 0; j < 32; j++)
        wcol2[j] = pk(pe_w2[(2 * j) * 64 + h], pe_w2[(2 * j + 1) * 64 + h]);
    __syncthreads();

    int b  = blockIdx.x >> 9;            // 512 blocks per batch
    int g0 = (blockIdx.x & 511) << 3;    // 8 voxels per block
    const float step = 2.0f / 15.0f;

    float accv[8];

#pragma unroll 1
    for (int v = 0; v < 8; v++) {
        int g = g0 + v;
        int gi = g >> 8, gj = (g >> 4) & 15, gk = g & 15;
        float gx = -1.0f + step * gi;
        float gy = -1.0f + step * gj;
        float gz = -1.0f + step * gk;

        const int* ib = g_idx + (b * GG + g) * KNN;
        float acc = 0.0f;
#pragma unroll 1
        for (int k = 0; k < KNN; k++) {
            int n = ib[k];
            const float* pp = pos + ((size_t)b * NPTS + n) * 3;
            float rx = pp[0] - gx, ry = pp[1] - gy, rz = pp[2] - gz;
            float t1 = rx * s_w1[h] + ry * s_w1[64 + h] + rz * s_w1[128 + h] + s_b1[h];
            s_t[h] = gelu_tanh(t1);
            __syncthreads();
            ull a2 = 0;
#pragma unroll
            for (int j = 0; j < 32; j++) a2 = fma2(pk2(((const float2*)s_t)[j]), wcol2[j], a2);
            float plo, phi; upk(a2, plo, phi);
            float pe = plo + phi + s_b2[h];
            const float* xp = xf + ((size_t)b * NPTS + n) * 3;
            float fm = xp[0] * s_fw[h] + xp[1] * s_fw[64 + h] + xp[2] * s_fw[128 + h] + s_fb[h];
            acc = fmaf(pe, fm, acc);
            __syncthreads();
        }
        accv[v] = acc * 0.125f;
    }

    // reload register columns with up_w, run the 8 update dots
#pragma unroll
    for (int j = 0; j < 32; j++)
        wcol2[j] = pk(up_w[(2 * j) * 64 + h], up_w[(2 * j + 1) * 64 + h]);

#pragma unroll 1
    for (int v = 0; v < 8; v++) {
        s_t[h] = accv[v];
        __syncthreads();
        ull a2 = 0;
#pragma unroll
        for (int j = 0; j < 32; j++) a2 = fma2(pk2(((const float2*)s_t)[j]), wcol2[j], a2);
        float olo, ohi; upk(a2, olo, ohi);
        float o = gelu_tanh(olo + ohi + s_ub[h]);

        int g = g0 + v;
        int s = (g & 15) * 256 + ((g >> 4) & 15) * 16 + (g >> 8);
        g_vol[(b * 64 + h) * GG + s] = o;
        __syncthreads();
    }
}

// ---------------- Conv3D 3x3x3 SAME, 64->64 ch, scalar FFMA, z-slab split ----------------
template <int R, int ZB, int COP>
__global__ void conv3d_kernel(int in_id, const float* __restrict__ w,
                              const float* __restrict__ bias, int out_id,
                              int in_stat, int out_stat) {
    constexpr int XS = R / 2;
    constexpr int PX = R + 4;          // padded row (16B-aligned rows)
    constexpr int PY = R + 2;
    constexpr int PZ = ZB + 2;
    constexpr int NT = 2 * R * ZB;
    constexpr int S  = R * R * R;
    constexpr int CELLS = PZ * R * R;

    __shared__ __align__(16) float sl[PZ * PY * PX];
    __shared__ __align__(16) float4 wsh4[COP * 64 * 9];

    const float* in = pick(in_id);
    float* out = pick(out_id);

    int tid = threadIdx.x;
    int co0 = blockIdx.x * COP;
    int z0  = blockIdx.y * ZB;
    int b   = blockIdx.z;

#pragma unroll
    for (int it = 0; it < (COP * 64 * 9) / NT; it++) {
        int i = tid + it * NT;
        int c = i / 576, rem = i - c * 576;
        const float* wp = w + (co0 + c) * 1728 + rem * 3;
        wsh4[i] = make_float4(wp[0], wp[1], wp[2], 0.0f);
    }
    for (int i = tid; i < PZ * PY * PX; i += NT) sl[i] = 0.0f;

    int xh = tid & 1;
    int y  = (tid >> 1) & (R - 1);
    int zl = tid / (2 * R);

    float acc[COP][XS];
#pragma unroll
    for (int c = 0; c < COP; c++)
#pragma unroll
        for (int x = 0; x < XS; x++) acc[c][x] = 0.0f;

    const float invc = 1.0f / (float)(BB * S);

    for (int ci = 0; ci < 64; ci++) {
        float mean = 0.0f, rstd = 0.0f;
        if (in_stat >= 0) {
            float m = g_st1[in_stat * 64 + ci] * invc;
            float v = g_st2[in_stat * 64 + ci] * invc - m * m;
            mean = m; rstd = rsqrtf(v + EPSBN);
        }
        __syncthreads();
        const float* ip = in + (size_t)(b * 64 + ci) * S;
#pragma unroll
        for (int it = 0; it < CELLS / NT; it++) {
            int i = tid + it * NT;
            int zz = i / (R * R), rem = i - zz * (R * R);
            int yy = rem / R, xx = rem - yy * R;
            int gz = z0 - 1 + zz;
            if (gz >= 0 && gz < R) {
                float v = ip[gz * R * R + yy * R + xx];
                if (in_stat >= 0) v = fmaxf((v - mean) * rstd, 0.0f);
                sl[(zz * PY + (yy + 1)) * PX + (xx + 1)] = v;
            }
        }
        __syncthreads();

#pragma unroll
        for (int dz = 0; dz < 3; dz++) {
#pragma unroll
            for (int dy = 0; dy < 3; dy++) {
                const float* base = &sl[((zl + dz) * PY + (y + dy)) * PX + xh * XS];
                float r[XS + 4];
#pragma unroll
                for (int q = 0; q < (XS + 4) / 4; q++)
                    *(float4*)&r[4 * q] = *(const float4*)&base[4 * q];
#pragma unroll
                for (int c = 0; c < COP; c++) {
                    float4 wv = wsh4[(c * 64 + ci) * 9 + dz * 3 + dy];
#pragma unroll
                    for (int x = 0; x < XS; x++)
                        acc[c][x] = fmaf(wv.x, r[x],
                                    fmaf(wv.y, r[x + 1],
                                    fmaf(wv.z, r[x + 2], acc[c][x])));
                }
            }
        }
    }

    int lane = tid & 31;
#pragma unroll
    for (int c = 0; c < COP; c++) {
        float bv = bias[co0 + c];
        float* op = out + (size_t)(b * 64 + co0 + c) * S + (z0 + zl) * R * R + y * R + xh * XS;
        float s1 = 0.0f, s2 = 0.0f;
#pragma unroll
        for (int x = 0; x < XS; x++) {
            float v = acc[c][x] + bv;
            acc[c][x] = v;
            s1 += v; s2 += v * v;
        }
#pragma unroll
        for (int q = 0; q < XS / 4; q++)
            *(float4*)&op[4 * q] = *(float4*)&acc[c][4 * q];
#pragma unroll
        for (int off = 16; off; off >>= 1) {
            s1 += __shfl_xor_sync(0xffffffffu, s1, off);
            s2 += __shfl_xor_sync(0xffffffffu, s2, off);
        }
        if (lane == 0) {
            atomicAdd(&g_st1[out_stat * 64 + co0 + c], s1);
            atomicAdd(&g_st2[out_stat * 64 + co0 + c], s2);
        }
    }
}

// ---------------- residual add (BN stat 1) + ReLU + maxpool ----------------
__global__ void respool_kernel() {
    int i = blockIdx.x * blockDim.x + threadIdx.x;
    if (i >= BB * 64 * 512) return;
    int x = i & 7, y = (i >> 3) & 7, z = (i >> 6) & 7, bc = i >> 9;
    int c = bc & 63;
    const float invc = 1.0f / (float)(BB * 4096);
    float m = g_st1[64 + c] * invc;
    float v = g_st2[64 + c] * invc - m * m;
    float r = rsqrtf(v + EPSBN);
    const float* vp = g_vol + (size_t)bc * 4096;
    const float* hp = g_h1 + (size_t)bc * 4096;
    float mx = -3.4e38f;
#pragma unroll
    for (int dz = 0; dz < 2; dz++)
#pragma unroll
        for (int dy = 0; dy < 2; dy++)
#pragma unroll
            for (int dx = 0; dx < 2; dx++) {
                int idx = (2 * z + dz) * 256 + (2 * y + dy) * 16 + (2 * x + dx);
                float t = fmaxf(vp[idx] + (hp[idx] - m) * r, 0.0f);
                mx = fmaxf(mx, t);
            }
    g_vol8[i] = mx;
}

// ---------------- final: residual(BN stat3)+ReLU, BN over result, affine, pool ------
__global__ void final_kernel(const float* __restrict__ on_g, const float* __restrict__ on_b) {
    __shared__ float sres[2048];
    __shared__ float rb1[8], rb2[8];
    __shared__ float smr[2];

    int c = blockIdx.x;
    int t = threadIdx.x;
    const float invc = 1.0f / (float)(BB * 512);
    float m3 = g_st1[3 * 64 + c] * invc;
    float v3 = g_st2[3 * 64 + c] * invc - m3 * m3;
    float r3 = rsqrtf(v3 + EPSBN);

    float s1 = 0.0f, s2 = 0.0f;
    for (int i = t; i < 2048; i += 256) {
        int b = i >> 9, s = i & 511;
        size_t off = (size_t)(b * 64 + c) * 512 + s;
        float val = fmaxf(g_vol8[off] + (g_h1[off] - m3) * r3, 0.0f);
        sres[i] = val;
        s1 += val; s2 += val * val;
    }
    int w = t >> 5, l = t & 31;
#pragma unroll
    for (int off = 16; off; off >>= 1) {
        s1 += __shfl_xor_sync(0xffffffffu, s1, off);
        s2 += __shfl_xor_sync(0xffffffffu, s2, off);
    }
    if (l == 0) { rb1[w] = s1; rb2[w] = s2; }
    __syncthreads();
    if (t == 0) {
        float a = 0.0f, q = 0.0f;
#pragma unroll
        for (int j = 0; j < 8; j++) { a += rb1[j]; q += rb2[j]; }
        float m4 = a * invc;
        float v4 = q * invc - m4 * m4;
        smr[0] = m4; smr[1] = rsqrtf(v4 + EPSBN);
    }
    __syncthreads();
    float m4 = smr[0], r4 = smr[1];

    if (w < 4) {
        float s = 0.0f;
#pragma unroll
        for (int k = 0; k < 16; k++) s += sres[w * 512 + l + k * 32];
#pragma unroll
        for (int off = 16; off; off >>= 1) s += __shfl_xor_sync(0xffffffffu, s, off);
        if (l == 0)
            g_pooled[w * 64 + c] = (s * (1.0f / 512.0f) - m4) * r4 * on_g[c] + on_b[c];
    }
}

// ---------------- head ----------------
__global__ void head_kernel(const float* __restrict__ ro_w, const float* __restrict__ ro_b,
                            float* __restrict__ out) {
    int t = threadIdx.x;
    int b = t >> 4, o = t & 15;
    float a = ro_b[o];
#pragma unroll
    for (int j = 0; j < 64; j++) a = fmaf(g_pooled[b * 64 + j], ro_w[j * 16 + o], a);
    out[b * 16 + o] = a;
}

// ---------------- launch ----------------
extern "C" void kernel_launch(void* const* d_in, const int* in_sizes, int n_in,
                              void* d_out, int out_size) {
    const float* pos   = (const float*)d_in[0];
    const float* xf    = (const float*)d_in[1];
    const float* pe_w1 = (const float*)d_in[2];
    const float* pe_b1 = (const float*)d_in[3];
    const float* pe_w2 = (const float*)d_in[4];
    const float* pe_b2 = (const float*)d_in[5];
    const float* f_w   = (const float*)d_in[6];
    const float* f_b   = (const float*)d_in[7];
    const float* up_w  = (const float*)d_in[8];
    const float* up_b  = (const float*)d_in[9];
    const float* conv_w= (const float*)d_in[10];
    const float* conv_b= (const float*)d_in[11];
    const float* on_g  = (const float*)d_in[12];
    const float* on_b  = (const float*)d_in[13];
    const float* ro_w  = (const float*)d_in[14];
    const float* ro_b  = (const float*)d_in[15];
    float* out = (float*)d_out;

    const int W1 = 64 * 64 * 27;

    knn_kernel<<<256, 128>>>(pos);
    mlp_kernel<<<2048, 64>>>(pos, xf, pe_w1, pe_b1, pe_w2, pe_b2, f_w, f_b, up_w, up_b);

    // block 0 (16^3): convA -> stats0 ; convB (norm stats0 on load) -> stats1
    conv3d_kernel<16, 4, 4><<<dim3(16, 4, 4), 128>>>(0, conv_w + 0 * W1, conv_b + 0,  1, -1, 0);
    conv3d_kernel<16, 4, 4><<<dim3(16, 4, 4), 128>>>(1, conv_w + 1 * W1, conv_b + 64, 2,  0, 1);
    respool_kernel<<<512, 256>>>();

    // block 1 (8^3): convC -> stats2 ; convD (norm stats2) -> stats3
    conv3d_kernel<8, 4, 2><<<dim3(32, 2, 4), 64>>>(3, conv_w + 2 * W1, conv_b + 128, 1, -1, 2);
    conv3d_kernel<8, 4, 2><<<dim3(32, 2, 4), 64>>>(1, conv_w + 3 * W1, conv_b + 192, 2,  2, 3);

    final_kernel<<<64, 256>>>(on_g, on_b);
    head_kernel<<<1, 64>>>(ro_w, ro_b, out);
}

// round 12
// speedup vs baseline: 1.3492x; 1.3492x over previous
#include <cuda_runtime.h>
#include <math.h>

#define BB   4
#define NPTS 4096
#define GG   4096
#define KNN  8
#define HH   64
#define EPSBN 1e-5f

// ---------------- scratch (static device globals; no allocations) ----------------
__device__ int   g_idx [BB*GG*KNN];
__device__ float g_vol [BB*HH*GG];     // buffer id 0
__device__ float g_tmp [BB*HH*GG];     // buffer id 1
__device__ float g_h1  [BB*HH*GG];     // buffer id 2
__device__ float g_vol8[BB*HH*512];    // buffer id 3
__device__ float g_st1 [6*64];         // per-channel sum   (stat slots)
__device__ float g_st2 [6*64];         // per-channel sumsq
__device__ float g_pooled[BB*64];

__device__ __forceinline__ float* pick(int id) {
    switch (id) {
        case 0: return g_vol;
        case 1: return g_tmp;
        case 2: return g_h1;
        default: return g_vol8;
    }
}

__device__ __forceinline__ float gelu_tanh(float x) {
    float x3 = x * x * x;
    float t  = tanhf(0.7978845608028654f * (x + 0.044715f * x3));
    return 0.5f * x * (1.0f + t);
}

// -------- packed f32x2 helpers --------
typedef unsigned long long ull;
__device__ __forceinline__ ull pk(float lo, float hi) {
    ull r; asm("mov.b64 %0, {%1,%2};" : "=l"(r) : "f"(lo), "f"(hi)); return r;
}
__device__ __forceinline__ ull pk2(float2 f) { return pk(f.x, f.y); }
__device__ __forceinline__ void upk(ull v, float& lo, float& hi) {
    asm("mov.b64 {%0,%1}, %2;" : "=f"(lo), "=f"(hi) : "l"(v));
}
__device__ __forceinline__ ull fma2(ull a, ull b, ull c) {
    ull d; asm("fma.rn.f32x2 %0, %1, %2, %3;" : "=l"(d) : "l"(a), "l"(b), "l"(c)); return d;
}

// ---------------- KNN: 2 threads per voxel, stable merge ----------------
__global__ void knn_kernel(const float* __restrict__ pos) {
    __shared__ float4 tile[2][64];
    __shared__ float  sbd[128][KNN];
    __shared__ int    sbi[128][KNN];

    if (blockIdx.x == 0) {
        for (int i = threadIdx.x; i < 6 * 64; i += 128) { g_st1[i] = 0.0f; g_st2[i] = 0.0f; }
    }

    int b   = blockIdx.x >> 6;
    int vl  = threadIdx.x & 63;
    int half= threadIdx.x >> 6;
    int g   = ((blockIdx.x & 63) << 6) + vl;

    int gi = g >> 8, gj = (g >> 4) & 15, gk = g & 15;
    const float step = 2.0f / 15.0f;
    float gx = -1.0f + step * gi;
    float gy = -1.0f + step * gj;
    float gz = -1.0f + step * gk;
    float ax = -2.0f * gx, ay = -2.0f * gy, az = -2.0f * gz;

    float bd[KNN]; int bi[KNN];
#pragma unroll
    for (int j = 0; j < KNN; j++) { bd[j] = 3.4e38f; bi[j] = 0; }

    const float* pb = pos + ((size_t)b * NPTS + half * 2048) * 3;

    for (int t0 = 0; t0 < 2048; t0 += 64) {
        __syncthreads();
        {
            int n = t0 + vl;
            float px = pb[n * 3 + 0], py = pb[n * 3 + 1], pz = pb[n * 3 + 2];
            tile[half][vl] = make_float4(px, py, pz, px * px + py * py + pz * pz);
        }
        __syncthreads();
#pragma unroll 2
        for (int t = 0; t < 64; t += 2) {
            float4 p = tile[half][t];
            float4 q = tile[half][t + 1];
            float e0 = fmaf(ax, p.x, fmaf(ay, p.y, fmaf(az, p.z, p.w)));
            float e1 = fmaf(ax, q.x, fmaf(ay, q.y, fmaf(az, q.z, q.w)));
            if (e0 < bd[KNN - 1]) {
                int n = half * 2048 + t0 + t;
#pragma unroll
                for (int j = KNN - 1; j >= 1; --j) {
                    if (e0 < bd[j - 1])  { bd[j] = bd[j - 1]; bi[j] = bi[j - 1]; }
                    else if (e0 < bd[j]) { bd[j] = e0;        bi[j] = n; }
                }
                if (e0 < bd[0]) { bd[0] = e0; bi[0] = n; }
            }
            if (e1 < bd[KNN - 1]) {
                int n = half * 2048 + t0 + t + 1;
#pragma unroll
                for (int j = KNN - 1; j >= 1; --j) {
                    if (e1 < bd[j - 1])  { bd[j] = bd[j - 1]; bi[j] = bi[j - 1]; }
                    else if (e1 < bd[j]) { bd[j] = e1;        bi[j] = n; }
                }
                if (e1 < bd[0]) { bd[0] = e1; bi[0] = n; }
            }
        }
    }

#pragma unroll
    for (int j = 0; j < KNN; j++) { sbd[threadIdx.x][j] = bd[j]; sbi[threadIdx.x][j] = bi[j]; }
    __syncthreads();

    if (threadIdx.x < 64) {
        int ia = 0, ibp = 0;
        int base = (b * GG + g) * KNN;
#pragma unroll
        for (int j = 0; j < KNN; j++) {
            float eA = sbd[threadIdx.x][ia], eB = sbd[threadIdx.x + 64][ibp];
            if (eA <= eB) { g_idx[base + j] = sbi[threadIdx.x][ia]; ia++; }
            else          { g_idx[base + j] = sbi[threadIdx.x + 64][ibp]; ibp++; }
        }
    }
}

// ---------------- Bipartite conv MLP: 8 voxels per block (weights amortized) --------
__global__ void mlp_kernel(const float* __restrict__ pos, const float* __restrict__ xf,
                           const float* __restrict__ pe_w1, const float* __restrict__ pe_b1,
                           const float* __restrict__ pe_w2, const float* __restrict__ pe_b2,
                           const float* __restrict__ f_w,   const float* __restrict__ f_b,
                           const float* __restrict__ up_w,  const float* __restrict__ up_b) {
    __shared__ float s_w1[192], s_fw[192];
    __shared__ float s_b1[64], s_b2[64], s_fb[64], s_ub[64];
    __shared__ __align__(8) float s_t[64];

    int h = threadIdx.x;
    s_w1[h] = pe_w1[h];       s_w1[h + 64] = pe_w1[h + 64];   s_w1[h + 128] = pe_w1[h + 128];
    s_fw[h] = f_w[h];         s_fw[h + 64] = f_w[h + 64];     s_fw[h + 128] = f_w[h + 128];
    s_b1[h] = pe_b1[h]; s_b2[h] = pe_b2[h]; s_fb[h] = f_b[h]; s_ub[h] = up_b[h];

    ull wcol2[32];
#pragma unroll
    for (int j = 0; j < 32; j++)
        wcol2[j] = pk(pe_w2[(2 * j) * 64 + h], pe_w2[(2 * j + 1) * 64 + h]);
    __syncthreads();

    int b  = blockIdx.x >> 9;
    int g0 = (blockIdx.x & 511) << 3;
    const float step = 2.0f / 15.0f;

    float accv[8];

#pragma unroll 1
    for (int v = 0; v < 8; v++) {
        int g = g0 + v;
        int gi = g >> 8, gj = (g >> 4) & 15, gk = g & 15;
        float gx = -1.0f + step * gi;
        float gy = -1.0f + step * gj;
        float gz = -1.0f + step * gk;

        const int* ib = g_idx + (b * GG + g) * KNN;
        float acc = 0.0f;
#pragma unroll 1
        for (int k = 0; k < KNN; k++) {
            int n = ib[k];
            const float* pp = pos + ((size_t)b * NPTS + n) * 3;
            float rx = pp[0] - gx, ry = pp[1] - gy, rz = pp[2] - gz;
            float t1 = rx * s_w1[h] + ry * s_w1[64 + h] + rz * s_w1[128 + h] + s_b1[h];
            s_t[h] = gelu_tanh(t1);
            __syncthreads();
            ull a2 = 0;
#pragma unroll
            for (int j = 0; j < 32; j++) a2 = fma2(pk2(((const float2*)s_t)[j]), wcol2[j], a2);
            float plo, phi; upk(a2, plo, phi);
            float pe = plo + phi + s_b2[h];
            const float* xp = xf + ((size_t)b * NPTS + n) * 3;
            float fm = xp[0] * s_fw[h] + xp[1] * s_fw[64 + h] + xp[2] * s_fw[128 + h] + s_fb[h];
            acc = fmaf(pe, fm, acc);
            __syncthreads();
        }
        accv[v] = acc * 0.125f;
    }

#pragma unroll
    for (int j = 0; j < 32; j++)
        wcol2[j] = pk(up_w[(2 * j) * 64 + h], up_w[(2 * j + 1) * 64 + h]);

#pragma unroll 1
    for (int v = 0; v < 8; v++) {
        s_t[h] = accv[v];
        __syncthreads();
        ull a2 = 0;
#pragma unroll
        for (int j = 0; j < 32; j++) a2 = fma2(pk2(((const float2*)s_t)[j]), wcol2[j], a2);
        float olo, ohi; upk(a2, olo, ohi);
        float o = gelu_tanh(olo + ohi + s_ub[h]);

        int g = g0 + v;
        int s = (g & 15) * 256 + ((g >> 4) & 15) * 16 + (g >> 8);
        g_vol[(b * 64 + h) * GG + s] = o;
        __syncthreads();
    }
}

// ---------------- Conv3D 16^3, co-pair packed f32x2, z-pair row reuse ----------------
// Thread = (xh, y, zp): 8-x strip, z-pair {z0+2zp, z0+2zp+1}, output channels
// {2cp, 2cp+1} packed in f32x2 lanes. Block 128 thr covers ZB=8 slab for one co-pair.
// Grid: (32 co-pairs, 2 slabs, 4 b). Weights pre-packed (co0,co1) in smem (broadcast).
// Staged plane-rows are loaded+splatted once and feed both z outputs via dz.
__global__ __launch_bounds__(128) void conv16p_kernel(
        int in_id, const float* __restrict__ w, const float* __restrict__ bias,
        int out_id, int in_stat, int out_stat) {
    constexpr int R  = 16;
    constexpr int PX = 20, PY = 18, PZ = 10;   // ZB=8 slab + halo
    constexpr int NT = 128;
    constexpr int S  = R * R * R;

    __shared__ __align__(16) float sl[PZ * PY * PX];
    __shared__ ull wsh[64 * 27];               // (ci,tap) -> packed (co0,co1)

    const float* in = pick(in_id);
    float* out = pick(out_id);

    int tid = threadIdx.x;
    int cp  = blockIdx.x;
    int co0 = cp * 2;
    int z0  = blockIdx.y * 8;
    int b   = blockIdx.z;

    for (int i = tid; i < 64 * 27; i += NT) {
        float w0 = w[(size_t)co0 * 1728 + i];
        float w1 = w[(size_t)(co0 + 1) * 1728 + i];
        wsh[i] = pk(w0, w1);
    }
    for (int i = tid; i < PZ * PY * PX; i += NT) sl[i] = 0.0f;

    int xh = tid & 1;
    int y  = (tid >> 1) & 15;
    int zp = tid >> 5;                          // warp id = z-pair id

    ull acc2[2][8];
#pragma unroll
    for (int zl = 0; zl < 2; zl++)
#pragma unroll
        for (int x = 0; x < 8; x++) acc2[zl][x] = 0;

    const float invc = 1.0f / (float)(BB * S);

    for (int ci = 0; ci < 64; ci++) {
        float mean = 0.0f, rstd = 0.0f;
        if (in_stat >= 0) {
            float m = g_st1[in_stat * 64 + ci] * invc;
            float v = g_st2[in_stat * 64 + ci] * invc - m * m;
            mean = m; rstd = rsqrtf(v + EPSBN);
        }
        __syncthreads();
        const float* ip = in + (size_t)(b * 64 + ci) * S;
#pragma unroll
        for (int it = 0; it < (PZ * 256) / NT; it++) {
            int i = tid + it * NT;
            int zz = i >> 8, rem = i & 255;
            int yy = rem >> 4, xx = rem & 15;
            int gz = z0 - 1 + zz;
            if (gz >= 0 && gz < R) {
                float v = ip[gz * 256 + rem];
                if (in_stat >= 0) v = fmaxf((v - mean) * rstd, 0.0f);
                sl[(zz * PY + (yy + 1)) * PX + (xx + 1)] = v;
            }
        }
        __syncthreads();

#pragma unroll
        for (int p = 0; p < 4; p++) {           // staged planes serving this z-pair
            int zz = zp * 2 + p;
#pragma unroll
            for (int dy = 0; dy < 3; dy++) {
                const float* base = &sl[(zz * PY + (y + dy)) * PX + xh * 8];
                float r[12];
#pragma unroll
                for (int q = 0; q < 3; q++)
                    *(float4*)&r[4 * q] = *(const float4*)&base[4 * q];
                ull s[10];
#pragma unroll
                for (int i = 0; i < 10; i++) s[i] = pk(r[i], r[i]);
#pragma unroll
                for (int zl = 0; zl < 2; zl++) {
                    int dz = p - zl;
                    if (dz < 0 || dz > 2) continue;   // compile-time pruned
                    const ull* wp = &wsh[ci * 27 + (dz * 3 + dy) * 3];
                    ull W0 = wp[0], W1 = wp[1], W2 = wp[2];
#pragma unroll
                    for (int x = 0; x < 8; x++)
                        acc2[zl][x] = fma2(W0, s[x],
                                      fma2(W1, s[x + 1],
                                      fma2(W2, s[x + 2], acc2[zl][x])));
                }
            }
        }
    }

    // epilogue: bias, store both channels, per-channel stats
    float bv0 = bias[co0], bv1 = bias[co0 + 1];
    float s1a = 0.0f, s2a = 0.0f, s1b = 0.0f, s2b = 0.0f;
#pragma unroll
    for (int zl = 0; zl < 2; zl++) {
        int z = z0 + zp * 2 + zl;
        float o0[8], o1[8];
#pragma unroll
        for (int x = 0; x < 8; x++) {
            float lo, hi; upk(acc2[zl][x], lo, hi);
            lo += bv0; hi += bv1;
            o0[x] = lo; o1[x] = hi;
            s1a += lo; s2a += lo * lo;
            s1b += hi; s2b += hi * hi;
        }
        float* op0 = out + (size_t)(b * 64 + co0) * S + z * 256 + y * 16 + xh * 8;
        float* op1 = out + (size_t)(b * 64 + co0 + 1) * S + z * 256 + y * 16 + xh * 8;
        *(float4*)&op0[0] = *(float4*)&o0[0];
        *(float4*)&op0[4] = *(float4*)&o0[4];
        *(float4*)&op1[0] = *(float4*)&o1[0];
        *(float4*)&op1[4] = *(float4*)&o1[4];
    }
#pragma unroll
    for (int off = 16; off; off >>= 1) {
        s1a += __shfl_xor_sync(0xffffffffu, s1a, off);
        s2a += __shfl_xor_sync(0xffffffffu, s2a, off);
        s1b += __shfl_xor_sync(0xffffffffu, s1b, off);
        s2b += __shfl_xor_sync(0xffffffffu, s2b, off);
    }
    if ((tid & 31) == 0) {
        atomicAdd(&g_st1[out_stat * 64 + co0],     s1a);
        atomicAdd(&g_st2[out_stat * 64 + co0],     s2a);
        atomicAdd(&g_st1[out_stat * 64 + co0 + 1], s1b);
        atomicAdd(&g_st2[out_stat * 64 + co0 + 1], s2b);
    }
}

// ---------------- Conv3D scalar template (used for 8^3 convs) ----------------
template <int R, int ZB, int COP>
__global__ void conv3d_kernel(int in_id, const float* __restrict__ w,
                              const float* __restrict__ bias, int out_id,
                              int in_stat, int out_stat) {
    constexpr int XS = R / 2;
    constexpr int PX = R + 4;
    constexpr int PY = R + 2;
    constexpr int PZ = ZB + 2;
    constexpr int NT = 2 * R * ZB;
    constexpr int S  = R * R * R;
    constexpr int CELLS = PZ * R * R;

    __shared__ __align__(16) float sl[PZ * PY * PX];
    __shared__ __align__(16) float4 wsh4[COP * 64 * 9];

    const float* in = pick(in_id);
    float* out = pick(out_id);

    int tid = threadIdx.x;
    int co0 = blockIdx.x * COP;
    int z0  = blockIdx.y * ZB;
    int b   = blockIdx.z;

#pragma unroll
    for (int it = 0; it < (COP * 64 * 9) / NT; it++) {
        int i = tid + it * NT;
        int c = i / 576, rem = i - c * 576;
        const float* wp = w + (co0 + c) * 1728 + rem * 3;
        wsh4[i] = make_float4(wp[0], wp[1], wp[2], 0.0f);
    }
    for (int i = tid; i < PZ * PY * PX; i += NT) sl[i] = 0.0f;

    int xh = tid & 1;
    int y  = (tid >> 1) & (R - 1);
    int zl = tid / (2 * R);

    float acc[COP][XS];
#pragma unroll
    for (int c = 0; c < COP; c++)
#pragma unroll
        for (int x = 0; x < XS; x++) acc[c][x] = 0.0f;

    const float invc = 1.0f / (float)(BB * S);

    for (int ci = 0; ci < 64; ci++) {
        float mean = 0.0f, rstd = 0.0f;
        if (in_stat >= 0) {
            float m = g_st1[in_stat * 64 + ci] * invc;
            float v = g_st2[in_stat * 64 + ci] * invc - m * m;
            mean = m; rstd = rsqrtf(v + EPSBN);
        }
        __syncthreads();
        const float* ip = in + (size_t)(b * 64 + ci) * S;
#pragma unroll
        for (int it = 0; it < CELLS / NT; it++) {
            int i = tid + it * NT;
            int zz = i / (R * R), rem = i - zz * (R * R);
            int yy = rem / R, xx = rem - yy * R;
            int gz = z0 - 1 + zz;
            if (gz >= 0 && gz < R) {
                float v = ip[gz * R * R + yy * R + xx];
                if (in_stat >= 0) v = fmaxf((v - mean) * rstd, 0.0f);
                sl[(zz * PY + (yy + 1)) * PX + (xx + 1)] = v;
            }
        }
        __syncthreads();

#pragma unroll
        for (int dz = 0; dz < 3; dz++) {
#pragma unroll
            for (int dy = 0; dy < 3; dy++) {
                const float* base = &sl[((zl + dz) * PY + (y + dy)) * PX + xh * XS];
                float r[XS + 4];
#pragma unroll
                for (int q = 0; q < (XS + 4) / 4; q++)
                    *(float4*)&r[4 * q] = *(const float4*)&base[4 * q];
#pragma unroll
                for (int c = 0; c < COP; c++) {
                    float4 wv = wsh4[(c * 64 + ci) * 9 + dz * 3 + dy];
#pragma unroll
                    for (int x = 0; x < XS; x++)
                        acc[c][x] = fmaf(wv.x, r[x],
                                    fmaf(wv.y, r[x + 1],
                                    fmaf(wv.z, r[x + 2], acc[c][x])));
                }
            }
        }
    }

    int lane = tid & 31;
#pragma unroll
    for (int c = 0; c < COP; c++) {
        float bv = bias[co0 + c];
        float* op = out + (size_t)(b * 64 + co0 + c) * S + (z0 + zl) * R * R + y * R + xh * XS;
        float s1 = 0.0f, s2 = 0.0f;
#pragma unroll
        for (int x = 0; x < XS; x++) {
            float v = acc[c][x] + bv;
            acc[c][x] = v;
            s1 += v; s2 += v * v;
        }
#pragma unroll
        for (int q = 0; q < XS / 4; q++)
            *(float4*)&op[4 * q] = *(float4*)&acc[c][4 * q];
#pragma unroll
        for (int off = 16; off; off >>= 1) {
            s1 += __shfl_xor_sync(0xffffffffu, s1, off);
            s2 += __shfl_xor_sync(0xffffffffu, s2, off);
        }
        if (lane == 0) {
            atomicAdd(&g_st1[out_stat * 64 + co0 + c], s1);
            atomicAdd(&g_st2[out_stat * 64 + co0 + c], s2);
        }
    }
}

// ---------------- residual add (BN stat 1) + ReLU + maxpool ----------------
__global__ void respool_kernel() {
    int i = blockIdx.x * blockDim.x + threadIdx.x;
    if (i >= BB * 64 * 512) return;
    int x = i & 7, y = (i >> 3) & 7, z = (i >> 6) & 7, bc = i >> 9;
    int c = bc & 63;
    const float invc = 1.0f / (float)(BB * 4096);
    float m = g_st1[64 + c] * invc;
    float v = g_st2[64 + c] * invc - m * m;
    float r = rsqrtf(v + EPSBN);
    const float* vp = g_vol + (size_t)bc * 4096;
    const float* hp = g_h1 + (size_t)bc * 4096;
    float mx = -3.4e38f;
#pragma unroll
    for (int dz = 0; dz < 2; dz++)
#pragma unroll
        for (int dy = 0; dy < 2; dy++)
#pragma unroll
            for (int dx = 0; dx < 2; dx++) {
                int idx = (2 * z + dz) * 256 + (2 * y + dy) * 16 + (2 * x + dx);
                float t = fmaxf(vp[idx] + (hp[idx] - m) * r, 0.0f);
                mx = fmaxf(mx, t);
            }
    g_vol8[i] = mx;
}

// ---------------- final: residual(BN stat3)+ReLU, BN over result, affine, pool ------
__global__ void final_kernel(const float* __restrict__ on_g, const float* __restrict__ on_b) {
    __shared__ float sres[2048];
    __shared__ float rb1[8], rb2[8];
    __shared__ float smr[2];

    int c = blockIdx.x;
    int t = threadIdx.x;
    const float invc = 1.0f / (float)(BB * 512);
    float m3 = g_st1[3 * 64 + c] * invc;
    float v3 = g_st2[3 * 64 + c] * invc - m3 * m3;
    float r3 = rsqrtf(v3 + EPSBN);

    float s1 = 0.0f, s2 = 0.0f;
    for (int i = t; i < 2048; i += 256) {
        int b = i >> 9, s = i & 511;
        size_t off = (size_t)(b * 64 + c) * 512 + s;
        float val = fmaxf(g_vol8[off] + (g_h1[off] - m3) * r3, 0.0f);
        sres[i] = val;
        s1 += val; s2 += val * val;
    }
    int w = t >> 5, l = t & 31;
#pragma unroll
    for (int off = 16; off; off >>= 1) {
        s1 += __shfl_xor_sync(0xffffffffu, s1, off);
        s2 += __shfl_xor_sync(0xffffffffu, s2, off);
    }
    if (l == 0) { rb1[w] = s1; rb2[w] = s2; }
    __syncthreads();
    if (t == 0) {
        float a = 0.0f, q = 0.0f;
#pragma unroll
        for (int j = 0; j < 8; j++) { a += rb1[j]; q += rb2[j]; }
        float m4 = a * invc;
        float v4 = q * invc - m4 * m4;
        smr[0] = m4; smr[1] = rsqrtf(v4 + EPSBN);
    }
    __syncthreads();
    float m4 = smr[0], r4 = smr[1];

    if (w < 4) {
        float s = 0.0f;
#pragma unroll
        for (int k = 0; k < 16; k++) s += sres[w * 512 + l + k * 32];
#pragma unroll
        for (int off = 16; off; off >>= 1) s += __shfl_xor_sync(0xffffffffu, s, off);
        if (l == 0)
            g_pooled[w * 64 + c] = (s * (1.0f / 512.0f) - m4) * r4 * on_g[c] + on_b[c];
    }
}

// ---------------- head ----------------
__global__ void head_kernel(const float* __restrict__ ro_w, const float* __restrict__ ro_b,
                            float* __restrict__ out) {
    int t = threadIdx.x;
    int b = t >> 4, o = t & 15;
    float a = ro_b[o];
#pragma unroll
    for (int j = 0; j < 64; j++) a = fmaf(g_pooled[b * 64 + j], ro_w[j * 16 + o], a);
    out[b * 16 + o] = a;
}

// ---------------- launch ----------------
extern "C" void kernel_launch(void* const* d_in, const int* in_sizes, int n_in,
                              void* d_out, int out_size) {
    const float* pos   = (const float*)d_in[0];
    const float* xf    = (const float*)d_in[1];
    const float* pe_w1 = (const float*)d_in[2];
    const float* pe_b1 = (const float*)d_in[3];
    const float* pe_w2 = (const float*)d_in[4];
    const float* pe_b2 = (const float*)d_in[5];
    const float* f_w   = (const float*)d_in[6];
    const float* f_b   = (const float*)d_in[7];
    const float* up_w  = (const float*)d_in[8];
    const float* up_b  = (const float*)d_in[9];
    const float* conv_w= (const float*)d_in[10];
    const float* conv_b= (const float*)d_in[11];
    const float* on_g  = (const float*)d_in[12];
    const float* on_b  = (const float*)d_in[13];
    const float* ro_w  = (const float*)d_in[14];
    const float* ro_b  = (const float*)d_in[15];
    float* out = (float*)d_out;

    const int W1 = 64 * 64 * 27;

    knn_kernel<<<256, 128>>>(pos);
    mlp_kernel<<<2048, 64>>>(pos, xf, pe_w1, pe_b1, pe_w2, pe_b2, f_w, f_b, up_w, up_b);

    // block 0 (16^3): convA -> stats0 ; convB (norm stats0 on load) -> stats1
    conv16p_kernel<<<dim3(32, 2, 4), 128>>>(0, conv_w + 0 * W1, conv_b + 0,  1, -1, 0);
    conv16p_kernel<<<dim3(32, 2, 4), 128>>>(1, conv_w + 1 * W1, conv_b + 64, 2,  0, 1);
    respool_kernel<<<512, 256>>>();

    // block 1 (8^3): convC -> stats2 ; convD (norm stats2) -> stats3
    conv3d_kernel<8, 4, 2><<<dim3(32, 2, 4), 64>>>(3, conv_w + 2 * W1, conv_b + 128, 1, -1, 2);
    conv3d_kernel<8, 4, 2><<<dim3(32, 2, 4), 64>>>(1, conv_w + 3 * W1, conv_b + 192, 2,  2, 3);

    final_kernel<<<64, 256>>>(on_g, on_b);
    head_kernel<<<1, 64>>>(ro_w, ro_b, out);
}

// round 17
// speedup vs baseline: 1.3960x; 1.0347x over previous
#include <cuda_runtime.h>
#include <math.h>

#define BB   4
#define NPTS 4096
#define GG   4096
#define KNN  8
#define HH   64
#define EPSBN 1e-5f

// ---------------- scratch (static device globals; no allocations) ----------------
__device__ int   g_idx [BB*GG*KNN];
__device__ float g_vol [BB*HH*GG];     // buffer id 0
__device__ float g_tmp [BB*HH*GG];     // buffer id 1
__device__ float g_h1  [BB*HH*GG];     // buffer id 2
__device__ float g_vol8[BB*HH*512];    // buffer id 3
__device__ float g_st1 [6*64];         // per-channel sum   (stat slots)
__device__ float g_st2 [6*64];         // per-channel sumsq
__device__ float g_pooled[BB*64];

__device__ __forceinline__ float* pick(int id) {
    switch (id) {
        case 0: return g_vol;
        case 1: return g_tmp;
        case 2: return g_h1;
        default: return g_vol8;
    }
}

__device__ __forceinline__ float gelu_tanh(float x) {
    float x3 = x * x * x;
    float t  = tanhf(0.7978845608028654f * (x + 0.044715f * x3));
    return 0.5f * x * (1.0f + t);
}

// -------- packed f32x2 helpers --------
typedef unsigned long long ull;
__device__ __forceinline__ ull pk(float lo, float hi) {
    ull r; asm("mov.b64 %0, {%1,%2};" : "=l"(r) : "f"(lo), "f"(hi)); return r;
}
__device__ __forceinline__ ull pk2(float2 f) { return pk(f.x, f.y); }
__device__ __forceinline__ void upk(ull v, float& lo, float& hi) {
    asm("mov.b64 {%0,%1}, %2;" : "=f"(lo), "=f"(hi) : "l"(v));
}
__device__ __forceinline__ ull fma2(ull a, ull b, ull c) {
    ull d; asm("fma.rn.f32x2 %0, %1, %2, %3;" : "=l"(d) : "l"(a), "l"(b), "l"(c)); return d;
}

// ---------------- KNN: 2 threads per voxel, stable merge ----------------
__global__ void knn_kernel(const float* __restrict__ pos) {
    __shared__ float4 tile[2][64];
    __shared__ float  sbd[128][KNN];
    __shared__ int    sbi[128][KNN];

    if (blockIdx.x == 0) {
        for (int i = threadIdx.x; i < 6 * 64; i += 128) { g_st1[i] = 0.0f; g_st2[i] = 0.0f; }
    }

    int b   = blockIdx.x >> 6;
    int vl  = threadIdx.x & 63;
    int half= threadIdx.x >> 6;
    int g   = ((blockIdx.x & 63) << 6) + vl;

    int gi = g >> 8, gj = (g >> 4) & 15, gk = g & 15;
    const float step = 2.0f / 15.0f;
    float gx = -1.0f + step * gi;
    float gy = -1.0f + step * gj;
    float gz = -1.0f + step * gk;
    float ax = -2.0f * gx, ay = -2.0f * gy, az = -2.0f * gz;

    float bd[KNN]; int bi[KNN];
#pragma unroll
    for (int j = 0; j < KNN; j++) { bd[j] = 3.4e38f; bi[j] = 0; }

    const float* pb = pos + ((size_t)b * NPTS + half * 2048) * 3;

    for (int t0 = 0; t0 < 2048; t0 += 64) {
        __syncthreads();
        {
            int n = t0 + vl;
            float px = pb[n * 3 + 0], py = pb[n * 3 + 1], pz = pb[n * 3 + 2];
            tile[half][vl] = make_float4(px, py, pz, px * px + py * py + pz * pz);
        }
        __syncthreads();
#pragma unroll 2
        for (int t = 0; t < 64; t += 2) {
            float4 p = tile[half][t];
            float4 q = tile[half][t + 1];
            float e0 = fmaf(ax, p.x, fmaf(ay, p.y, fmaf(az, p.z, p.w)));
            float e1 = fmaf(ax, q.x, fmaf(ay, q.y, fmaf(az, q.z, q.w)));
            if (e0 < bd[KNN - 1]) {
                int n = half * 2048 + t0 + t;
#pragma unroll
                for (int j = KNN - 1; j >= 1; --j) {
                    if (e0 < bd[j - 1])  { bd[j] = bd[j - 1]; bi[j] = bi[j - 1]; }
                    else if (e0 < bd[j]) { bd[j] = e0;        bi[j] = n; }
                }
                if (e0 < bd[0]) { bd[0] = e0; bi[0] = n; }
            }
            if (e1 < bd[KNN - 1]) {
                int n = half * 2048 + t0 + t + 1;
#pragma unroll
                for (int j = KNN - 1; j >= 1; --j) {
                    if (e1 < bd[j - 1])  { bd[j] = bd[j - 1]; bi[j] = bi[j - 1]; }
                    else if (e1 < bd[j]) { bd[j] = e1;        bi[j] = n; }
                }
                if (e1 < bd[0]) { bd[0] = e1; bi[0] = n; }
            }
        }
    }

#pragma unroll
    for (int j = 0; j < KNN; j++) { sbd[threadIdx.x][j] = bd[j]; sbi[threadIdx.x][j] = bi[j]; }
    __syncthreads();

    if (threadIdx.x < 64) {
        int ia = 0, ibp = 0;
        int base = (b * GG + g) * KNN;
#pragma unroll
        for (int j = 0; j < KNN; j++) {
            float eA = sbd[threadIdx.x][ia], eB = sbd[threadIdx.x + 64][ibp];
            if (eA <= eB) { g_idx[base + j] = sbi[threadIdx.x][ia]; ia++; }
            else          { g_idx[base + j] = sbi[threadIdx.x + 64][ibp]; ibp++; }
        }
    }
}

// ---------------- Bipartite conv MLP: 8 voxels per block (weights amortized) --------
__global__ void mlp_kernel(const float* __restrict__ pos, const float* __restrict__ xf,
                           const float* __restrict__ pe_w1, const float* __restrict__ pe_b1,
                           const float* __restrict__ pe_w2, const float* __restrict__ pe_b2,
                           const float* __restrict__ f_w,   const float* __restrict__ f_b,
                           const float* __restrict__ up_w,  const float* __restrict__ up_b) {
    __shared__ float s_w1[192], s_fw[192];
    __shared__ float s_b1[64], s_b2[64], s_fb[64], s_ub[64];
    __shared__ __align__(8) float s_t[64];

    int h = threadIdx.x;
    s_w1[h] = pe_w1[h];       s_w1[h + 64] = pe_w1[h + 64];   s_w1[h + 128] = pe_w1[h + 128];
    s_fw[h] = f_w[h];         s_fw[h + 64] = f_w[h + 64];     s_fw[h + 128] = f_w[h + 128];
    s_b1[h] = pe_b1[h]; s_b2[h] = pe_b2[h]; s_fb[h] = f_b[h]; s_ub[h] = up_b[h];

    ull wcol2[32];
#pragma unroll
    for (int j = 0; j < 32; j++)
        wcol2[j] = pk(pe_w2[(2 * j) * 64 + h], pe_w2[(2 * j + 1) * 64 + h]);
    __syncthreads();

    int b  = blockIdx.x >> 9;
    int g0 = (blockIdx.x & 511) << 3;
    const float step = 2.0f / 15.0f;

    float accv[8];

#pragma unroll 1
    for (int v = 0; v < 8; v++) {
        int g = g0 + v;
        int gi = g >> 8, gj = (g >> 4) & 15, gk = g & 15;
        float gx = -1.0f + step * gi;
        float gy = -1.0f + step * gj;
        float gz = -1.0f + step * gk;

        const int* ib = g_idx + (b * GG + g) * KNN;
        float acc = 0.0f;
#pragma unroll 1
        for (int k = 0; k < KNN; k++) {
            int n = ib[k];
            const float* pp = pos + ((size_t)b * NPTS + n) * 3;
            float rx = pp[0] - gx, ry = pp[1] - gy, rz = pp[2] - gz;
            float t1 = rx * s_w1[h] + ry * s_w1[64 + h] + rz * s_w1[128 + h] + s_b1[h];
            s_t[h] = gelu_tanh(t1);
            __syncthreads();
            ull a2 = 0;
#pragma unroll
            for (int j = 0; j < 32; j++) a2 = fma2(pk2(((const float2*)s_t)[j]), wcol2[j], a2);
            float plo, phi; upk(a2, plo, phi);
            float pe = plo + phi + s_b2[h];
            const float* xp = xf + ((size_t)b * NPTS + n) * 3;
            float fm = xp[0] * s_fw[h] + xp[1] * s_fw[64 + h] + xp[2] * s_fw[128 + h] + s_fb[h];
            acc = fmaf(pe, fm, acc);
            __syncthreads();
        }
        accv[v] = acc * 0.125f;
    }

#pragma unroll
    for (int j = 0; j < 32; j++)
        wcol2[j] = pk(up_w[(2 * j) * 64 + h], up_w[(2 * j + 1) * 64 + h]);

#pragma unroll 1
    for (int v = 0; v < 8; v++) {
        s_t[h] = accv[v];
        __syncthreads();
        ull a2 = 0;
#pragma unroll
        for (int j = 0; j < 32; j++) a2 = fma2(pk2(((const float2*)s_t)[j]), wcol2[j], a2);
        float olo, ohi; upk(a2, olo, ohi);
        float o = gelu_tanh(olo + ohi + s_ub[h]);

        int g = g0 + v;
        int s = (g & 15) * 256 + ((g >> 4) & 15) * 16 + (g >> 8);
        g_vol[(b * 64 + h) * GG + s] = o;
        __syncthreads();
    }
}

// ---------------- Conv3D 16^3, co-pair f32x2, z-pair reuse, pipelined staging -------
// Thread = (xh, y, zp). Double-buffered smem slab: prefetch ci+1 cells into regs
// (LDG batch), compute ci from buf[cur], store prefetch into buf[nxt], ONE barrier.
__global__ __launch_bounds__(128) void conv16p_kernel(
        int in_id, const float* __restrict__ w, const float* __restrict__ bias,
        int out_id, int in_stat, int out_stat) {
    constexpr int R  = 16;
    constexpr int PX = 20, PY = 18, PZ = 10;   // ZB=8 slab + halo
    constexpr int NT = 128;
    constexpr int S  = R * R * R;
    constexpr int SLAB = PZ * PY * PX;         // 3600
    constexpr int PF = (PZ * 256) / NT;        // 20 staged cells per thread

    __shared__ __align__(16) float sl[2][SLAB];
    __shared__ ull wsh[64 * 27];

    const float* in = pick(in_id);
    float* out = pick(out_id);

    int tid = threadIdx.x;
    int cp  = blockIdx.x;
    int co0 = cp * 2;
    int z0  = blockIdx.y * 8;
    int b   = blockIdx.z;

    for (int i = tid; i < 64 * 27; i += NT) {
        float w0 = w[(size_t)co0 * 1728 + i];
        float w1 = w[(size_t)(co0 + 1) * 1728 + i];
        wsh[i] = pk(w0, w1);
    }
    for (int i = tid; i < SLAB; i += NT) { sl[0][i] = 0.0f; sl[1][i] = 0.0f; }

    int xh = tid & 1;
    int y  = (tid >> 1) & 15;
    int zp = tid >> 5;                          // warp id = z-pair id

    ull acc2[2][8];
#pragma unroll
    for (int zl = 0; zl < 2; zl++)
#pragma unroll
        for (int x = 0; x < 8; x++) acc2[zl][x] = 0;

    const float invc = 1.0f / (float)(BB * S);

    // ---- staging helpers (prefetch to regs / store regs to smem) ----
    float pf[PF];
    auto stage_load = [&](int ci) {
        float mean = 0.0f, rstd = 0.0f;
        if (in_stat >= 0) {
            float m = g_st1[in_stat * 64 + ci] * invc;
            float v = g_st2[in_stat * 64 + ci] * invc - m * m;
            mean = m; rstd = rsqrtf(v + EPSBN);
        }
        const float* ip = in + (size_t)(b * 64 + ci) * S;
#pragma unroll
        for (int it = 0; it < PF; it++) {
            int i = tid + it * NT;
            int zz = i >> 8, rem = i & 255;
            int gz = z0 - 1 + zz;
            float v = 0.0f;
            if (gz >= 0 && gz < R) {
                v = ip[gz * 256 + rem];
                if (in_stat >= 0) v = fmaxf((v - mean) * rstd, 0.0f);
            }
            pf[it] = v;
        }
    };
    auto stage_store = [&](float* buf) {
#pragma unroll
        for (int it = 0; it < PF; it++) {
            int i = tid + it * NT;
            int zz = i >> 8, rem = i & 255;
            int yy = rem >> 4, xx = rem & 15;
            buf[(zz * PY + (yy + 1)) * PX + (xx + 1)] = pf[it];
        }
    };

    stage_load(0);
    __syncthreads();           // zeroing complete everywhere
    stage_store(sl[0]);
    __syncthreads();

#pragma unroll 1
    for (int ci = 0; ci < 64; ci++) {
        const float* cur = sl[ci & 1];
        if (ci < 63) stage_load(ci + 1);       // LDGs in flight during compute

#pragma unroll
        for (int p = 0; p < 4; p++) {           // staged planes serving this z-pair
            int zz = zp * 2 + p;
#pragma unroll
            for (int dy = 0; dy < 3; dy++) {
                const float* base = &cur[(zz * PY + (y + dy)) * PX + xh * 8];
                float r[12];
#pragma unroll
                for (int q = 0; q < 3; q++)
                    *(float4*)&r[4 * q] = *(const float4*)&base[4 * q];
                ull s[10];
#pragma unroll
                for (int i = 0; i < 10; i++) s[i] = pk(r[i], r[i]);
#pragma unroll
                for (int zl = 0; zl < 2; zl++) {
                    int dz = p - zl;
                    if (dz < 0 || dz > 2) continue;   // compile-time pruned
                    const ull* wp = &wsh[ci * 27 + (dz * 3 + dy) * 3];
                    ull W0 = wp[0], W1 = wp[1], W2 = wp[2];
#pragma unroll
                    for (int x = 0; x < 8; x++)
                        acc2[zl][x] = fma2(W0, s[x],
                                      fma2(W1, s[x + 1],
                                      fma2(W2, s[x + 2], acc2[zl][x])));
                }
            }
        }

        if (ci < 63) stage_store((float*)sl[(ci + 1) & 1]);
        __syncthreads();
    }

    // epilogue: bias, store both channels, per-channel stats
    float bv0 = bias[co0], bv1 = bias[co0 + 1];
    float s1a = 0.0f, s2a = 0.0f, s1b = 0.0f, s2b = 0.0f;
#pragma unroll
    for (int zl = 0; zl < 2; zl++) {
        int z = z0 + zp * 2 + zl;
        float o0[8], o1[8];
#pragma unroll
        for (int x = 0; x < 8; x++) {
            float lo, hi; upk(acc2[zl][x], lo, hi);
            lo += bv0; hi += bv1;
            o0[x] = lo; o1[x] = hi;
            s1a += lo; s2a += lo * lo;
            s1b += hi; s2b += hi * hi;
        }
        float* op0 = out + (size_t)(b * 64 + co0) * S + z * 256 + y * 16 + xh * 8;
        float* op1 = out + (size_t)(b * 64 + co0 + 1) * S + z * 256 + y * 16 + xh * 8;
        *(float4*)&op0[0] = *(float4*)&o0[0];
        *(float4*)&op0[4] = *(float4*)&o0[4];
        *(float4*)&op1[0] = *(float4*)&o1[0];
        *(float4*)&op1[4] = *(float4*)&o1[4];
    }
#pragma unroll
    for (int off = 16; off; off >>= 1) {
        s1a += __shfl_xor_sync(0xffffffffu, s1a, off);
        s2a += __shfl_xor_sync(0xffffffffu, s2a, off);
        s1b += __shfl_xor_sync(0xffffffffu, s1b, off);
        s2b += __shfl_xor_sync(0xffffffffu, s2b, off);
    }
    if ((tid & 31) == 0) {
        atomicAdd(&g_st1[out_stat * 64 + co0],     s1a);
        atomicAdd(&g_st2[out_stat * 64 + co0],     s2a);
        atomicAdd(&g_st1[out_stat * 64 + co0 + 1], s1b);
        atomicAdd(&g_st2[out_stat * 64 + co0 + 1], s2b);
    }
}

// ---------------- Conv3D scalar template (8^3 convs), pipelined staging ----------------
template <int R, int ZB, int COP>
__global__ void conv3d_kernel(int in_id, const float* __restrict__ w,
                              const float* __restrict__ bias, int out_id,
                              int in_stat, int out_stat) {
    constexpr int XS = R / 2;
    constexpr int PX = R + 4;
    constexpr int PY = R + 2;
    constexpr int PZ = ZB + 2;
    constexpr int NT = 2 * R * ZB;
    constexpr int S  = R * R * R;
    constexpr int SLAB = PZ * PY * PX;
    constexpr int PF = (PZ * R * R) / NT;

    __shared__ __align__(16) float sl[2][SLAB];
    __shared__ __align__(16) float4 wsh4[COP * 64 * 9];

    const float* in = pick(in_id);
    float* out = pick(out_id);

    int tid = threadIdx.x;
    int co0 = blockIdx.x * COP;
    int z0  = blockIdx.y * ZB;
    int b   = blockIdx.z;

#pragma unroll
    for (int it = 0; it < (COP * 64 * 9) / NT; it++) {
        int i = tid + it * NT;
        int c = i / 576, rem = i - c * 576;
        const float* wp = w + (co0 + c) * 1728 + rem * 3;
        wsh4[i] = make_float4(wp[0], wp[1], wp[2], 0.0f);
    }
    for (int i = tid; i < SLAB; i += NT) { sl[0][i] = 0.0f; sl[1][i] = 0.0f; }

    int xh = tid & 1;
    int y  = (tid >> 1) & (R - 1);
    int zl = tid / (2 * R);

    float acc[COP][XS];
#pragma unroll
    for (int c = 0; c < COP; c++)
#pragma unroll
        for (int x = 0; x < XS; x++) acc[c][x] = 0.0f;

    const float invc = 1.0f / (float)(BB * S);

    float pf[PF];
    auto stage_load = [&](int ci) {
        float mean = 0.0f, rstd = 0.0f;
        if (in_stat >= 0) {
            float m = g_st1[in_stat * 64 + ci] * invc;
            float v = g_st2[in_stat * 64 + ci] * invc - m * m;
            mean = m; rstd = rsqrtf(v + EPSBN);
        }
        const float* ip = in + (size_t)(b * 64 + ci) * S;
#pragma unroll
        for (int it = 0; it < PF; it++) {
            int i = tid + it * NT;
            int zz = i / (R * R), rem = i - zz * (R * R);
            int gz = z0 - 1 + zz;
            float v = 0.0f;
            if (gz >= 0 && gz < R) {
                v = ip[gz * R * R + rem];
                if (in_stat >= 0) v = fmaxf((v - mean) * rstd, 0.0f);
            }
            pf[it] = v;
        }
    };
    auto stage_store = [&](float* buf) {
#pragma unroll
        for (int it = 0; it < PF; it++) {
            int i = tid + it * NT;
            int zz = i / (R * R), rem = i - zz * (R * R);
            int yy = rem / R, xx = rem - yy * R;
            buf[(zz * PY + (yy + 1)) * PX + (xx + 1)] = pf[it];
        }
    };

    stage_load(0);
    __syncthreads();
    stage_store(sl[0]);
    __syncthreads();

#pragma unroll 1
    for (int ci = 0; ci < 64; ci++) {
        const float* cur = sl[ci & 1];
        if (ci < 63) stage_load(ci + 1);

#pragma unroll
        for (int dz = 0; dz < 3; dz++) {
#pragma unroll
            for (int dy = 0; dy < 3; dy++) {
                const float* base = &cur[((zl + dz) * PY + (y + dy)) * PX + xh * XS];
                float r[XS + 4];
#pragma unroll
                for (int q = 0; q < (XS + 4) / 4; q++)
                    *(float4*)&r[4 * q] = *(const float4*)&base[4 * q];
#pragma unroll
                for (int c = 0; c < COP; c++) {
                    float4 wv = wsh4[(c * 64 + ci) * 9 + dz * 3 + dy];
#pragma unroll
                    for (int x = 0; x < XS; x++)
                        acc[c][x] = fmaf(wv.x, r[x],
                                    fmaf(wv.y, r[x + 1],
                                    fmaf(wv.z, r[x + 2], acc[c][x])));
                }
            }
        }

        if (ci < 63) stage_store((float*)sl[(ci + 1) & 1]);
        __syncthreads();
    }

    int lane = tid & 31;
#pragma unroll
    for (int c = 0; c < COP; c++) {
        float bv = bias[co0 + c];
        float* op = out + (size_t)(b * 64 + co0 + c) * S + (z0 + zl) * R * R + y * R + xh * XS;
        float s1 = 0.0f, s2 = 0.0f;
#pragma unroll
        for (int x = 0; x < XS; x++) {
            float v = acc[c][x] + bv;
            acc[c][x] = v;
            s1 += v; s2 += v * v;
        }
#pragma unroll
        for (int q = 0; q < XS / 4; q++)
            *(float4*)&op[4 * q] = *(float4*)&acc[c][4 * q];
#pragma unroll
        for (int off = 16; off; off >>= 1) {
            s1 += __shfl_xor_sync(0xffffffffu, s1, off);
            s2 += __shfl_xor_sync(0xffffffffu, s2, off);
        }
        if (lane == 0) {
            atomicAdd(&g_st1[out_stat * 64 + co0 + c], s1);
            atomicAdd(&g_st2[out_stat * 64 + co0 + c], s2);
        }
    }
}

// ---------------- residual add (BN stat 1) + ReLU + maxpool ----------------
__global__ void respool_kernel() {
    int i = blockIdx.x * blockDim.x + threadIdx.x;
    if (i >= BB * 64 * 512) return;
    int x = i & 7, y = (i >> 3) & 7, z = (i >> 6) & 7, bc = i >> 9;
    int c = bc & 63;
    const float invc = 1.0f / (float)(BB * 4096);
    float m = g_st1[64 + c] * invc;
    float v = g_st2[64 + c] * invc - m * m;
    float r = rsqrtf(v + EPSBN);
    const float* vp = g_vol + (size_t)bc * 4096;
    const float* hp = g_h1 + (size_t)bc * 4096;
    float mx = -3.4e38f;
#pragma unroll
    for (int dz = 0; dz < 2; dz++)
#pragma unroll
        for (int dy = 0; dy < 2; dy++)
#pragma unroll
            for (int dx = 0; dx < 2; dx++) {
                int idx = (2 * z + dz) * 256 + (2 * y + dy) * 16 + (2 * x + dx);
                float t = fmaxf(vp[idx] + (hp[idx] - m) * r, 0.0f);
                mx = fmaxf(mx, t);
            }
    g_vol8[i] = mx;
}

// ---------------- final: residual(BN stat3)+ReLU, BN over result, affine, pool ------
__global__ void final_kernel(const float* __restrict__ on_g, const float* __restrict__ on_b) {
    __shared__ float sres[2048];
    __shared__ float rb1[8], rb2[8];
    __shared__ float smr[2];

    int c = blockIdx.x;
    int t = threadIdx.x;
    const float invc = 1.0f / (float)(BB * 512);
    float m3 = g_st1[3 * 64 + c] * invc;
    float v3 = g_st2[3 * 64 + c] * invc - m3 * m3;
    float r3 = rsqrtf(v3 + EPSBN);

    float s1 = 0.0f, s2 = 0.0f;
    for (int i = t; i < 2048; i += 256) {
        int b = i >> 9, s = i & 511;
        size_t off = (size_t)(b * 64 + c) * 512 + s;
        float val = fmaxf(g_vol8[off] + (g_h1[off] - m3) * r3, 0.0f);
        sres[i] = val;
        s1 += val; s2 += val * val;
    }
    int w = t >> 5, l = t & 31;
#pragma unroll
    for (int off = 16; off; off >>= 1) {
        s1 += __shfl_xor_sync(0xffffffffu, s1, off);
        s2 += __shfl_xor_sync(0xffffffffu, s2, off);
    }
    if (l == 0) { rb1[w] = s1; rb2[w] = s2; }
    __syncthreads();
    if (t == 0) {
        float a = 0.0f, q = 0.0f;
#pragma unroll
        for (int j = 0; j < 8; j++) { a += rb1[j]; q += rb2[j]; }
        float m4 = a * invc;
        float v4 = q * invc - m4 * m4;
        smr[0] = m4; smr[1] = rsqrtf(v4 + EPSBN);
    }
    __syncthreads();
    float m4 = smr[0], r4 = smr[1];

    if (w < 4) {
        float s = 0.0f;
#pragma unroll
        for (int k = 0; k < 16; k++) s += sres[w * 512 + l + k * 32];
#pragma unroll
        for (int off = 16; off; off >>= 1) s += __shfl_xor_sync(0xffffffffu, s, off);
        if (l == 0)
            g_pooled[w * 64 + c] = (s * (1.0f / 512.0f) - m4) * r4 * on_g[c] + on_b[c];
    }
}

// ---------------- head ----------------
__global__ void head_kernel(const float* __restrict__ ro_w, const float* __restrict__ ro_b,
                            float* __restrict__ out) {
    int t = threadIdx.x;
    int b = t >> 4, o = t & 15;
    float a = ro_b[o];
#pragma unroll
    for (int j = 0; j < 64; j++) a = fmaf(g_pooled[b * 64 + j], ro_w[j * 16 + o], a);
    out[b * 16 + o] = a;
}

// ---------------- launch ----------------
extern "C" void kernel_launch(void* const* d_in, const int* in_sizes, int n_in,
                              void* d_out, int out_size) {
    const float* pos   = (const float*)d_in[0];
    const float* xf    = (const float*)d_in[1];
    const float* pe_w1 = (const float*)d_in[2];
    const float* pe_b1 = (const float*)d_in[3];
    const float* pe_w2 = (const float*)d_in[4];
    const float* pe_b2 = (const float*)d_in[5];
    const float* f_w   = (const float*)d_in[6];
    const float* f_b   = (const float*)d_in[7];
    const float* up_w  = (const float*)d_in[8];
    const float* up_b  = (const float*)d_in[9];
    const float* conv_w= (const float*)d_in[10];
    const float* conv_b= (const float*)d_in[11];
    const float* on_g  = (const float*)d_in[12];
    const float* on_b  = (const float*)d_in[13];
    const float* ro_w  = (const float*)d_in[14];
    const float* ro_b  = (const float*)d_in[15];
    float* out = (float*)d_out;

    const int W1 = 64 * 64 * 27;

    knn_kernel<<<256, 128>>>(pos);
    mlp_kernel<<<2048, 64>>>(pos, xf, pe_w1, pe_b1, pe_w2, pe_b2, f_w, f_b, up_w, up_b);

    // block 0 (16^3): convA -> stats0 ; convB (norm stats0 on load) -> stats1
    conv16p_kernel<<<dim3(32, 2, 4), 128>>>(0, conv_w + 0 * W1, conv_b + 0,  1, -1, 0);
    conv16p_kernel<<<dim3(32, 2, 4), 128>>>(1, conv_w + 1 * W1, conv_b + 64, 2,  0, 1);
    respool_kernel<<<512, 256>>>();

    // block 1 (8^3): convC -> stats2 ; convD (norm stats2) -> stats3
    conv3d_kernel<8, 4, 2><<<dim3(32, 2, 4), 64>>>(3, conv_w + 2 * W1, conv_b + 128, 1, -1, 2);
    conv3d_kernel<8, 4, 2><<<dim3(32, 2, 4), 64>>>(1, conv_w + 3 * W1, conv_b + 192, 2,  2, 3);

    final_kernel<<<64, 256>>>(on_g, on_b);
    head_kernel<<<1, 64>>>(ro_w, ro_b, out);
}